// round 1
// baseline (speedup 1.0000x reference)
#include <cuda_runtime.h>
#include <cuda_bf16.h>
#include <cstdint>

// Problem constants
#define MAXN 100000
#define DIN  128
#define HDIM 128
#define CDIM 47

// Device scratch (allocation-free rule: __device__ globals)
__device__ float g_h1[(size_t)MAXN * HDIM];
__device__ float g_h2[(size_t)MAXN * HDIM];
__device__ float g_hn[(size_t)MAXN * HDIM];
__device__ float g_invdeg[MAXN];
__device__ int   g_degcnt[MAXN];

// ---------------------------------------------------------------------------
// degree kernels
// ---------------------------------------------------------------------------
__global__ void zero_deg_kernel(int n) {
    int i = blockIdx.x * blockDim.x + threadIdx.x;
    if (i < n) g_degcnt[i] = 0;
}

__global__ void count_deg_kernel(const int* __restrict__ dst, int e) {
    int i = blockIdx.x * blockDim.x + threadIdx.x;
    if (i < e) atomicAdd(&g_degcnt[dst[i]], 1);
}

__global__ void inv_deg_kernel(int n) {
    int i = blockIdx.x * blockDim.x + threadIdx.x;
    if (i < n) {
        float d = (float)g_degcnt[i];
        g_invdeg[i] = 1.0f / fmaxf(d, 1.0f);
    }
}

// ---------------------------------------------------------------------------
// GEMM: out[r, c] = (relu?)A[r, :] @ W[:, c] (+ bias[c])
// A: nrows x 128 row-major, W: 128 x dout row-major.
// BM=64 rows, BN=64 cols per block, 256 threads, 4x4 microtile.
// ---------------------------------------------------------------------------
#define BM 64
#define BN 64
#define AS_LD 132   // padded row length for As[64][132]
#define BS_LD 68    // padded row length for Bs[128][68]

__global__ void gemm_kernel(const float* __restrict__ A,
                            const float* __restrict__ W,
                            const float* __restrict__ bias,
                            float* __restrict__ out,
                            int nrows, int dout, int do_relu) {
    extern __shared__ float smem[];
    float (*As)[AS_LD] = (float (*)[AS_LD])smem;                 // [64][132]
    float (*Bs)[BS_LD] = (float (*)[BS_LD])(smem + BM * AS_LD);  // [128][68]

    const int tid = threadIdx.x;
    const int tx = tid & 15;    // 0..15 -> 4 cols each
    const int ty = tid >> 4;    // 0..15 -> 4 rows each
    const int row0 = blockIdx.x * BM;
    const int col0 = blockIdx.y * BN;

    // Stage A tile: 64 rows x 128 cols, float4 loads
#pragma unroll
    for (int t = 0; t < 8; t++) {
        int f  = tid + t * 256;        // 0..2047 float4 slots
        int r  = f >> 5;               // 0..63
        int c4 = (f & 31) * 4;         // 0..124
        int row = row0 + r;
        float4 v = make_float4(0.f, 0.f, 0.f, 0.f);
        if (row < nrows) {
            v = *(const float4*)&A[(size_t)row * DIN + c4];
            if (do_relu) {
                v.x = fmaxf(v.x, 0.f); v.y = fmaxf(v.y, 0.f);
                v.z = fmaxf(v.z, 0.f); v.w = fmaxf(v.w, 0.f);
            }
        }
        *(float4*)&As[r][c4] = v;
    }

    // Stage B tile: 128 x 64 (scalar loads; dout may be 47)
#pragma unroll
    for (int t = 0; t < 32; t++) {
        int i = tid + t * 256;         // 0..8191
        int k = i >> 6;                // 0..127
        int n = i & 63;                // 0..63
        int ng = col0 + n;
        Bs[k][n] = (ng < dout) ? W[(size_t)k * dout + ng] : 0.0f;
    }
    __syncthreads();

    float acc[4][4];
#pragma unroll
    for (int i = 0; i < 4; i++)
#pragma unroll
        for (int j = 0; j < 4; j++) acc[i][j] = 0.0f;

#pragma unroll 4
    for (int k = 0; k < DIN; k++) {
        float4 b = *(const float4*)&Bs[k][tx * 4];
        float a0 = As[ty * 4 + 0][k];
        float a1 = As[ty * 4 + 1][k];
        float a2 = As[ty * 4 + 2][k];
        float a3 = As[ty * 4 + 3][k];
        acc[0][0] += a0 * b.x; acc[0][1] += a0 * b.y; acc[0][2] += a0 * b.z; acc[0][3] += a0 * b.w;
        acc[1][0] += a1 * b.x; acc[1][1] += a1 * b.y; acc[1][2] += a1 * b.z; acc[1][3] += a1 * b.w;
        acc[2][0] += a2 * b.x; acc[2][1] += a2 * b.y; acc[2][2] += a2 * b.z; acc[2][3] += a2 * b.w;
        acc[3][0] += a3 * b.x; acc[3][1] += a3 * b.y; acc[3][2] += a3 * b.z; acc[3][3] += a3 * b.w;
    }

#pragma unroll
    for (int i = 0; i < 4; i++) {
        int row = row0 + ty * 4 + i;
        if (row >= nrows) continue;
#pragma unroll
        for (int j = 0; j < 4; j++) {
            int col = col0 + tx * 4 + j;
            if (col < dout) {
                float v = acc[i][j];
                if (bias) v += bias[col];
                out[(size_t)row * dout + col] = v;
            }
        }
    }
}

// ---------------------------------------------------------------------------
// Scatter-add: out[dst, :] += hn[src, :] * invdeg[dst]
// warp per edge; 128-wide uses float4 vector red; 47-wide scalar red.
// ---------------------------------------------------------------------------
__device__ __forceinline__ void red_add_v4(float* p, float x, float y, float z, float w) {
    asm volatile("red.global.add.v4.f32 [%0], {%1, %2, %3, %4};"
                 :: "l"(p), "f"(x), "f"(y), "f"(z), "f"(w) : "memory");
}

__global__ void scatter128_kernel(const float* __restrict__ hn,
                                  const int* __restrict__ src,
                                  const int* __restrict__ dst,
                                  float* __restrict__ out, int e) {
    long long gid = (long long)blockIdx.x * blockDim.x + threadIdx.x;
    int edge = (int)(gid >> 5);
    if (edge >= e) return;
    int lane = (int)(gid & 31);
    int s = __ldg(&src[edge]);
    int d = __ldg(&dst[edge]);
    float inv = __ldg(&g_invdeg[d]);
    float4 v = *(const float4*)&hn[(size_t)s * 128 + lane * 4];
    red_add_v4(&out[(size_t)d * 128 + lane * 4],
               v.x * inv, v.y * inv, v.z * inv, v.w * inv);
}

__global__ void scatter47_kernel(const float* __restrict__ hn,
                                 const int* __restrict__ src,
                                 const int* __restrict__ dst,
                                 float* __restrict__ out, int e) {
    long long gid = (long long)blockIdx.x * blockDim.x + threadIdx.x;
    int edge = (int)(gid >> 5);
    if (edge >= e) return;
    int lane = (int)(gid & 31);
    int s = __ldg(&src[edge]);
    int d = __ldg(&dst[edge]);
    float inv = __ldg(&g_invdeg[d]);
    const float* hrow = &hn[(size_t)s * CDIM];
    float* orow = &out[(size_t)d * CDIM];
    atomicAdd(&orow[lane], hrow[lane] * inv);
    if (lane < CDIM - 32) {
        int c = lane + 32;
        atomicAdd(&orow[c], hrow[c] * inv);
    }
}

// ---------------------------------------------------------------------------
// launch
// ---------------------------------------------------------------------------
extern "C" void kernel_launch(void* const* d_in, const int* in_sizes, int n_in,
                              void* d_out, int out_size) {
    const float* x        = (const float*)d_in[0];
    const int*   src      = (const int*)d_in[1];
    const int*   dst      = (const int*)d_in[2];
    const float* w_self0  = (const float*)d_in[3];
    const float* w_neigh0 = (const float*)d_in[4];
    const float* b0       = (const float*)d_in[5];
    const float* w_self1  = (const float*)d_in[6];
    const float* w_neigh1 = (const float*)d_in[7];
    const float* b1       = (const float*)d_in[8];
    const float* w_self2  = (const float*)d_in[9];
    const float* w_neigh2 = (const float*)d_in[10];
    const float* b2       = (const float*)d_in[11];
    float* out = (float*)d_out;

    const int N = in_sizes[0] / DIN;
    const int E = in_sizes[1];

    void *p_h1, *p_h2, *p_hn;
    cudaGetSymbolAddress(&p_h1, g_h1);
    cudaGetSymbolAddress(&p_h2, g_h2);
    cudaGetSymbolAddress(&p_hn, g_hn);
    float* h1 = (float*)p_h1;
    float* h2 = (float*)p_h2;
    float* hn = (float*)p_hn;

    const int SMEM = (BM * AS_LD + 128 * BS_LD) * sizeof(float);  // ~68.6 KB
    cudaFuncSetAttribute(gemm_kernel, cudaFuncAttributeMaxDynamicSharedMemorySize, SMEM);

    dim3 blk(256);
    int nblk = (N + 255) / 256;
    int eblk = (E + 255) / 256;
    long long sthreads = (long long)E * 32;
    int sblk = (int)((sthreads + 255) / 256);

    // degrees -> invdeg
    zero_deg_kernel<<<nblk, blk>>>(N);
    count_deg_kernel<<<eblk, blk>>>(dst, E);
    inv_deg_kernel<<<nblk, blk>>>(N);

    dim3 g128((N + BM - 1) / BM, (HDIM + BN - 1) / BN);  // (1563, 2)
    dim3 g47((N + BM - 1) / BM, (CDIM + BN - 1) / BN);   // (1563, 1)

    // layer 0: x -> h1
    gemm_kernel<<<g128, blk, SMEM>>>(x, w_self0, b0, h1, N, HDIM, 0);
    gemm_kernel<<<g128, blk, SMEM>>>(x, w_neigh0, nullptr, hn, N, HDIM, 0);
    scatter128_kernel<<<sblk, blk>>>(hn, src, dst, h1, E);

    // layer 1: relu(h1) -> h2
    gemm_kernel<<<g128, blk, SMEM>>>(h1, w_self1, b1, h2, N, HDIM, 1);
    gemm_kernel<<<g128, blk, SMEM>>>(h1, w_neigh1, nullptr, hn, N, HDIM, 1);
    scatter128_kernel<<<sblk, blk>>>(hn, src, dst, h2, E);

    // layer 2: relu(h2) -> out (N x 47)
    gemm_kernel<<<g47, blk, SMEM>>>(h2, w_self2, b2, out, N, CDIM, 1);
    gemm_kernel<<<g47, blk, SMEM>>>(h2, w_neigh2, nullptr, hn, N, CDIM, 1);
    scatter47_kernel<<<sblk, blk>>>(hn, src, dst, out, E);
}

// round 6
// speedup vs baseline: 1.5629x; 1.5629x over previous
#include <cuda_runtime.h>
#include <cstdint>

#define MAXN 100000
#define MAXE 1700000
#define DIN  128
#define HDIM 128
#define CDIM 47
#define SCAN_B 256
#define NBLK_SCAN ((MAXN + SCAN_B - 1) / SCAN_B)

// ---------------- device scratch (allocation-free) ----------------
__device__ float g_h1[(size_t)MAXN * HDIM];
__device__ float g_h2[(size_t)MAXN * HDIM];
__device__ float g_hn[(size_t)MAXN * HDIM];
__device__ float g_invdeg[MAXN];
__device__ int   g_deg[MAXN];
__device__ int   g_rowstart[MAXN + 1];
__device__ int   g_cursor[MAXN];
__device__ int   g_esrc[MAXE];
__device__ int   g_bsum[NBLK_SCAN];
__device__ int   g_boff[NBLK_SCAN];

// ---------------- degree / CSR build ----------------
__global__ void zero_deg_kernel(int n) {
    int i = blockIdx.x * blockDim.x + threadIdx.x;
    if (i < n) g_deg[i] = 0;
}

__global__ void count_deg_kernel(const int* __restrict__ dst, int e) {
    int i = blockIdx.x * blockDim.x + threadIdx.x;
    if (i < e) atomicAdd(&g_deg[dst[i]], 1);
}

__global__ void inv_deg_kernel(int n) {
    int i = blockIdx.x * blockDim.x + threadIdx.x;
    if (i < n) g_invdeg[i] = 1.0f / fmaxf((float)g_deg[i], 1.0f);
}

// block-local exclusive scan of g_deg -> g_rowstart (partial), block sums -> g_bsum
__global__ void scan1_kernel(int n) {
    __shared__ int s[SCAN_B];
    int i = blockIdx.x * SCAN_B + threadIdx.x;
    int v = (i < n) ? g_deg[i] : 0;
    s[threadIdx.x] = v;
    __syncthreads();
    for (int off = 1; off < SCAN_B; off <<= 1) {
        int t = (threadIdx.x >= off) ? s[threadIdx.x - off] : 0;
        __syncthreads();
        s[threadIdx.x] += t;
        __syncthreads();
    }
    if (i < n) g_rowstart[i] = s[threadIdx.x] - v;   // exclusive within block
    if (threadIdx.x == SCAN_B - 1) g_bsum[blockIdx.x] = s[threadIdx.x];
}

// scan block sums (single block, nb <= 512)
__global__ void scan2_kernel(int nb) {
    __shared__ int s[512];
    int v = (threadIdx.x < nb) ? g_bsum[threadIdx.x] : 0;
    s[threadIdx.x] = v;
    __syncthreads();
    for (int off = 1; off < 512; off <<= 1) {
        int t = (threadIdx.x >= off) ? s[threadIdx.x - off] : 0;
        __syncthreads();
        s[threadIdx.x] += t;
        __syncthreads();
    }
    if (threadIdx.x < nb) g_boff[threadIdx.x] = s[threadIdx.x] - v;
}

__global__ void scan3_kernel(int n, int e) {
    int i = blockIdx.x * blockDim.x + threadIdx.x;
    if (i < n) {
        int r = g_rowstart[i] + g_boff[i / SCAN_B];
        g_rowstart[i] = r;
        g_cursor[i] = r;
    }
    if (i == 0) g_rowstart[n] = e;
}

__global__ void fill_kernel(const int* __restrict__ src, const int* __restrict__ dst, int e) {
    int i = blockIdx.x * blockDim.x + threadIdx.x;
    if (i < e) {
        int p = atomicAdd(&g_cursor[dst[i]], 1);
        g_esrc[p] = src[i];
    }
}

// ---------------- GEMM: out = (relu?)A @ W (+bias) ----------------
// A: nrows x 128 row-major. W: 128 x dout row-major. BM=128 rows/block.
// Register k-tiling (k+=4): A frags loaded as float4 along k (no smem transpose).
template<int BN, int NTH>
__global__ __launch_bounds__(NTH, 1)
void gemm_kernel(const float* __restrict__ A, const float* __restrict__ W,
                 const float* __restrict__ bias, float* __restrict__ out,
                 int nrows, int dout, int do_relu) {
    constexpr int BM = 128;
    constexpr int TN = 4;
    constexpr int CG = BN / TN;                 // col groups
    constexpr int TM = (BM * BN) / (NTH * TN);  // rows per thread (=8)
    extern __shared__ float smem[];
    float* As = smem;                // [BM][128]
    float* Bs = smem + BM * DIN;     // [128][BN]

    const int tid = threadIdx.x;
    const int tx = tid % CG;
    const int ty = tid / CG;
    const int row0 = blockIdx.x * BM;
    const int col0 = blockIdx.y * BN;

    // stage A: coalesced float4, optional relu
#pragma unroll
    for (int f = tid; f < BM * (DIN / 4); f += NTH) {
        int r = f >> 5;
        int c4 = (f & 31) * 4;
        int row = row0 + r;
        float4 v = make_float4(0.f, 0.f, 0.f, 0.f);
        if (row < nrows) {
            v = *(const float4*)&A[(size_t)row * DIN + c4];
            if (do_relu) {
                v.x = fmaxf(v.x, 0.f); v.y = fmaxf(v.y, 0.f);
                v.z = fmaxf(v.z, 0.f); v.w = fmaxf(v.w, 0.f);
            }
        }
        *(float4*)&As[r * DIN + c4] = v;
    }

    // stage B
    const bool bvec = (col0 + BN <= dout) && ((dout & 3) == 0);
#pragma unroll
    for (int f = tid; f < DIN * (BN / 4); f += NTH) {
        int k = f / (BN / 4);
        int c4 = (f % (BN / 4)) * 4;
        float4 v;
        if (bvec) {
            v = *(const float4*)&W[(size_t)k * dout + col0 + c4];
        } else {
            int c = col0 + c4;
            v.x = (c + 0 < dout) ? W[(size_t)k * dout + c + 0] : 0.f;
            v.y = (c + 1 < dout) ? W[(size_t)k * dout + c + 1] : 0.f;
            v.z = (c + 2 < dout) ? W[(size_t)k * dout + c + 2] : 0.f;
            v.w = (c + 3 < dout) ? W[(size_t)k * dout + c + 3] : 0.f;
        }
        *(float4*)&Bs[k * BN + c4] = v;
    }
    __syncthreads();

    float acc[TM][TN];
#pragma unroll
    for (int i = 0; i < TM; i++)
#pragma unroll
        for (int j = 0; j < TN; j++) acc[i][j] = 0.f;

#pragma unroll 2
    for (int k = 0; k < DIN; k += 4) {
        float4 a[TM];
#pragma unroll
        for (int i = 0; i < TM; i++)
            a[i] = *(const float4*)&As[(ty * TM + i) * DIN + k];
        float4 b[4];
#pragma unroll
        for (int kk = 0; kk < 4; kk++)
            b[kk] = *(const float4*)&Bs[(k + kk) * BN + tx * TN];
#pragma unroll
        for (int kk = 0; kk < 4; kk++) {
#pragma unroll
            for (int i = 0; i < TM; i++) {
                float av = (kk == 0) ? a[i].x : (kk == 1) ? a[i].y : (kk == 2) ? a[i].z : a[i].w;
                acc[i][0] += av * b[kk].x;
                acc[i][1] += av * b[kk].y;
                acc[i][2] += av * b[kk].z;
                acc[i][3] += av * b[kk].w;
            }
        }
    }

    // epilogue
    float bb[TN];
#pragma unroll
    for (int j = 0; j < TN; j++) {
        int c = col0 + tx * TN + j;
        bb[j] = (bias != nullptr && c < dout) ? bias[c] : 0.f;
    }
    const bool ovec = ((dout & 3) == 0) && (col0 + tx * TN + TN <= dout);
#pragma unroll
    for (int i = 0; i < TM; i++) {
        int row = row0 + ty * TM + i;
        if (row >= nrows) continue;
        if (ovec) {
            float4 o = make_float4(acc[i][0] + bb[0], acc[i][1] + bb[1],
                                   acc[i][2] + bb[2], acc[i][3] + bb[3]);
            *(float4*)&out[(size_t)row * dout + col0 + tx * TN] = o;
        } else {
#pragma unroll
            for (int j = 0; j < TN; j++) {
                int c = col0 + tx * TN + j;
                if (c < dout) out[(size_t)row * dout + c] = acc[i][j] + bb[j];
            }
        }
    }
}

// ---------------- CSR gather aggregation: out[d,:] += invdeg[d] * sum_j hn[src_j,:] ----
__global__ void gather128_kernel(const float* __restrict__ hn,
                                 float* __restrict__ out, int n) {
    int gid = blockIdx.x * blockDim.x + threadIdx.x;
    int node = gid >> 5;
    if (node >= n) return;
    int lane = gid & 31;
    int beg = g_rowstart[node];
    int end = g_rowstart[node + 1];
    float4 acc = make_float4(0.f, 0.f, 0.f, 0.f);
    int j = beg;
    for (; j + 1 < end; j += 2) {
        int s0 = __ldg(&g_esrc[j]);
        int s1 = __ldg(&g_esrc[j + 1]);
        float4 v0 = *(const float4*)&hn[(size_t)s0 * 128 + lane * 4];
        float4 v1 = *(const float4*)&hn[(size_t)s1 * 128 + lane * 4];
        acc.x += v0.x + v1.x; acc.y += v0.y + v1.y;
        acc.z += v0.z + v1.z; acc.w += v0.w + v1.w;
    }
    if (j < end) {
        int s0 = __ldg(&g_esrc[j]);
        float4 v0 = *(const float4*)&hn[(size_t)s0 * 128 + lane * 4];
        acc.x += v0.x; acc.y += v0.y; acc.z += v0.z; acc.w += v0.w;
    }
    float inv = g_invdeg[node];
    float4 o = *(float4*)&out[(size_t)node * 128 + lane * 4];
    o.x += acc.x * inv; o.y += acc.y * inv;
    o.z += acc.z * inv; o.w += acc.w * inv;
    *(float4*)&out[(size_t)node * 128 + lane * 4] = o;
}

__global__ void gather47_kernel(const float* __restrict__ hn,
                                float* __restrict__ out, int n) {
    int gid = blockIdx.x * blockDim.x + threadIdx.x;
    int node = gid >> 5;
    if (node >= n) return;
    int lane = gid & 31;
    int beg = g_rowstart[node];
    int end = g_rowstart[node + 1];
    float acc0 = 0.f, acc1 = 0.f;
    int c1 = lane + 32;
    bool has2 = (c1 < CDIM);
    for (int j = beg; j < end; j++) {
        int s = __ldg(&g_esrc[j]);
        const float* hr = &hn[(size_t)s * CDIM];
        acc0 += hr[lane];
        if (has2) acc1 += hr[c1];
    }
    float inv = g_invdeg[node];
    float* orow = &out[(size_t)node * CDIM];
    orow[lane] += acc0 * inv;
    if (has2) orow[c1] += acc1 * inv;
}

// ---------------- launch ----------------
extern "C" void kernel_launch(void* const* d_in, const int* in_sizes, int n_in,
                              void* d_out, int out_size) {
    const float* x        = (const float*)d_in[0];
    const int*   src      = (const int*)d_in[1];
    const int*   dst      = (const int*)d_in[2];
    const float* w_self0  = (const float*)d_in[3];
    const float* w_neigh0 = (const float*)d_in[4];
    const float* b0       = (const float*)d_in[5];
    const float* w_self1  = (const float*)d_in[6];
    const float* w_neigh1 = (const float*)d_in[7];
    const float* b1       = (const float*)d_in[8];
    const float* w_self2  = (const float*)d_in[9];
    const float* w_neigh2 = (const float*)d_in[10];
    const float* b2       = (const float*)d_in[11];
    float* out = (float*)d_out;

    const int N = in_sizes[0] / DIN;
    const int E = in_sizes[1];

    void *p_h1, *p_h2, *p_hn;
    cudaGetSymbolAddress(&p_h1, g_h1);
    cudaGetSymbolAddress(&p_h2, g_h2);
    cudaGetSymbolAddress(&p_hn, g_hn);
    float* h1 = (float*)p_h1;
    float* h2 = (float*)p_h2;
    float* hn = (float*)p_hn;

    const int SMEM128 = (128 * DIN + DIN * 128) * sizeof(float);  // 131072
    const int SMEM64  = (128 * DIN + DIN * 64)  * sizeof(float);  // 98304
    static bool attr_done = false;
    cudaFuncSetAttribute(gemm_kernel<128, 512>,
                         cudaFuncAttributeMaxDynamicSharedMemorySize, SMEM128);
    cudaFuncSetAttribute(gemm_kernel<64, 256>,
                         cudaFuncAttributeMaxDynamicSharedMemorySize, SMEM64);
    (void)attr_done;

    dim3 blk(256);
    int nblk = (N + 255) / 256;
    int eblk = (E + 255) / 256;
    int nb_scan = (N + SCAN_B - 1) / SCAN_B;
    long long gthreads = (long long)N * 32;
    int gblk = (int)((gthreads + 255) / 256);

    // degrees + CSR
    zero_deg_kernel<<<nblk, blk>>>(N);
    count_deg_kernel<<<eblk, blk>>>(dst, E);
    inv_deg_kernel<<<nblk, blk>>>(N);
    scan1_kernel<<<nb_scan, SCAN_B>>>(N);
    scan2_kernel<<<1, 512>>>(nb_scan);
    scan3_kernel<<<nblk, blk>>>(N, E);
    fill_kernel<<<eblk, blk>>>(src, dst, E);

    dim3 g128((N + 127) / 128, 1);

    // layer 0: x -> h1
    gemm_kernel<128, 512><<<g128, 512, SMEM128>>>(x, w_self0, b0, h1, N, HDIM, 0);
    gemm_kernel<128, 512><<<g128, 512, SMEM128>>>(x, w_neigh0, nullptr, hn, N, HDIM, 0);
    gather128_kernel<<<gblk, blk>>>(hn, h1, N);

    // layer 1: relu(h1) -> h2
    gemm_kernel<128, 512><<<g128, 512, SMEM128>>>(h1, w_self1, b1, h2, N, HDIM, 1);
    gemm_kernel<128, 512><<<g128, 512, SMEM128>>>(h1, w_neigh1, nullptr, hn, N, HDIM, 1);
    gather128_kernel<<<gblk, blk>>>(hn, h2, N);

    // layer 2: relu(h2) -> out (N x 47)
    gemm_kernel<64, 256><<<g128, 256, SMEM64>>>(h2, w_self2, b2, out, N, CDIM, 1);
    gemm_kernel<64, 256><<<g128, 256, SMEM64>>>(h2, w_neigh2, nullptr, hn, N, CDIM, 1);
    gather47_kernel<<<gblk, blk>>>(hn, out, N);
}

// round 10
// speedup vs baseline: 1.7422x; 1.1147x over previous
#include <cuda_runtime.h>
#include <cstdint>

#define MAXN 100000
#define MAXE 1700000
#define DIN  128
#define HDIM 128
#define CDIM 47
#define SCAN_B 256
#define NBLK_SCAN ((MAXN + SCAN_B - 1) / SCAN_B)

// ---------------- device scratch (allocation-free) ----------------
__device__ float g_h1[(size_t)MAXN * HDIM];
__device__ float g_h2[(size_t)MAXN * HDIM];
__device__ float g_hn[(size_t)MAXN * HDIM];
__device__ float g_invdeg[MAXN];
__device__ int   g_deg[MAXN];
__device__ int   g_rowstart[MAXN + 1];
__device__ int   g_cursor[MAXN];
__device__ int   g_esrc[MAXE];
__device__ int   g_bsum[NBLK_SCAN];
__device__ int   g_boff[NBLK_SCAN];

// ---------------- degree / CSR build ----------------
__global__ void zero_deg_kernel(int n) {
    int i = blockIdx.x * blockDim.x + threadIdx.x;
    if (i < n) g_deg[i] = 0;
}

__global__ void count_deg_kernel(const int* __restrict__ dst, int e) {
    int i = blockIdx.x * blockDim.x + threadIdx.x;
    if (i < e) atomicAdd(&g_deg[dst[i]], 1);
}

__global__ void inv_deg_kernel(int n) {
    int i = blockIdx.x * blockDim.x + threadIdx.x;
    if (i < n) g_invdeg[i] = 1.0f / fmaxf((float)g_deg[i], 1.0f);
}

__global__ void scan1_kernel(int n) {
    __shared__ int s[SCAN_B];
    int i = blockIdx.x * SCAN_B + threadIdx.x;
    int v = (i < n) ? g_deg[i] : 0;
    s[threadIdx.x] = v;
    __syncthreads();
    for (int off = 1; off < SCAN_B; off <<= 1) {
        int t = (threadIdx.x >= off) ? s[threadIdx.x - off] : 0;
        __syncthreads();
        s[threadIdx.x] += t;
        __syncthreads();
    }
    if (i < n) g_rowstart[i] = s[threadIdx.x] - v;
    if (threadIdx.x == SCAN_B - 1) g_bsum[blockIdx.x] = s[threadIdx.x];
}

__global__ void scan2_kernel(int nb) {
    __shared__ int s[512];
    int v = (threadIdx.x < nb) ? g_bsum[threadIdx.x] : 0;
    s[threadIdx.x] = v;
    __syncthreads();
    for (int off = 1; off < 512; off <<= 1) {
        int t = (threadIdx.x >= off) ? s[threadIdx.x - off] : 0;
        __syncthreads();
        s[threadIdx.x] += t;
        __syncthreads();
    }
    if (threadIdx.x < nb) g_boff[threadIdx.x] = s[threadIdx.x] - v;
}

__global__ void scan3_kernel(int n, int e) {
    int i = blockIdx.x * blockDim.x + threadIdx.x;
    if (i < n) {
        int r = g_rowstart[i] + g_boff[i / SCAN_B];
        g_rowstart[i] = r;
        g_cursor[i] = r;
    }
    if (i == 0) g_rowstart[n] = e;
}

__global__ void fill_kernel(const int* __restrict__ src, const int* __restrict__ dst, int e) {
    int i = blockIdx.x * blockDim.x + threadIdx.x;
    if (i < e) {
        int p = atomicAdd(&g_cursor[dst[i]], 1);
        g_esrc[p] = src[i];
    }
}

// ---------------- tf32 helpers ----------------
__device__ __forceinline__ uint32_t f2tf32(float x) {
    uint32_t r;
    asm("cvt.rna.tf32.f32 %0, %1;" : "=r"(r) : "f"(x));
    return r;
}

__device__ __forceinline__ void mma_tf32(float* c, const uint32_t* a, const uint32_t* b) {
    asm volatile(
        "mma.sync.aligned.m16n8k8.row.col.f32.tf32.tf32.f32 "
        "{%0,%1,%2,%3}, {%4,%5,%6,%7}, {%8,%9}, {%0,%1,%2,%3};"
        : "+f"(c[0]), "+f"(c[1]), "+f"(c[2]), "+f"(c[3])
        : "r"(a[0]), "r"(a[1]), "r"(a[2]), "r"(a[3]), "r"(b[0]), "r"(b[1]));
}

// ---------------- tf32 HMMA GEMM: out[r,c] = (relu?)A[r,:] @ W[:,c] (+bias) ----
// A: nrows x 128 row-major. W: 128 x DV row-major. BM=128 rows/block.
// As[128][LDA] tf32 bits, Bs[BN][LDB] n-major tf32 bits.
// blockIdx.y selects (W1,bias,out1) vs (W2,-,out2).
#define LDA 132
#define LDB 132

template<int BN, int DV>
__global__ __launch_bounds__(256, 1)
void mma_gemm_kernel(const float* __restrict__ A,
                     const float* __restrict__ W1, const float* __restrict__ W2,
                     const float* __restrict__ bias,
                     float* __restrict__ out1, float* __restrict__ out2,
                     int nrows, int do_relu) {
    extern __shared__ float smem[];
    float* As = smem;               // [128][LDA]
    float* Bs = smem + 128 * LDA;   // [BN][LDB]

    const int tid = threadIdx.x;
    const int row0 = blockIdx.x * 128;
    const bool selfhalf = (blockIdx.y == 0);
    const float* W = selfhalf ? W1 : W2;
    float* out = selfhalf ? out1 : out2;

    // ---- stage A: relu + tf32 round ----
    for (int f = tid; f < 128 * 32; f += 256) {
        int r = f >> 5;
        int c4 = (f & 31) * 4;
        int row = row0 + r;
        float4 v = make_float4(0.f, 0.f, 0.f, 0.f);
        if (row < nrows) {
            v = *(const float4*)&A[(size_t)row * DIN + c4];
            if (do_relu) {
                v.x = fmaxf(v.x, 0.f); v.y = fmaxf(v.y, 0.f);
                v.z = fmaxf(v.z, 0.f); v.w = fmaxf(v.w, 0.f);
            }
        }
        float* p = &As[r * LDA + c4];
        p[0] = __uint_as_float(f2tf32(v.x));
        p[1] = __uint_as_float(f2tf32(v.y));
        p[2] = __uint_as_float(f2tf32(v.z));
        p[3] = __uint_as_float(f2tf32(v.w));
    }

    // ---- stage B: Bs[n][k] = tf32(W[k][n]) (coalesced reads over n) ----
    for (int i = tid; i < 128 * BN; i += 256) {
        int n = i % BN;
        int k = i / BN;
        float v = (n < DV) ? W[(size_t)k * DV + n] : 0.f;
        Bs[n * LDB + k] = __uint_as_float(f2tf32(v));
    }
    __syncthreads();

    // ---- warp tiling ----
    constexpr int WN_CNT = BN / 64;        // 2 (BN=128) or 1 (BN=64)
    constexpr int WM_CNT = 8 / WN_CNT;     // 4 or 8
    constexpr int TMR = 128 / WM_CNT;      // 32 or 16 rows per warp
    constexpr int MI = TMR / 16;           // 2 or 1

    const int wid = tid >> 5;
    const int lane = tid & 31;
    const int g = lane >> 2;
    const int tig = lane & 3;
    const int wm = wid % WM_CNT;
    const int wn = wid / WM_CNT;
    const int mbase = wm * TMR;
    const int nbase = wn * 64;

    float acc[MI][8][4];
#pragma unroll
    for (int mi = 0; mi < MI; mi++)
#pragma unroll
        for (int ni = 0; ni < 8; ni++)
#pragma unroll
            for (int q = 0; q < 4; q++) acc[mi][ni][q] = 0.f;

#pragma unroll
    for (int k0 = 0; k0 < 16; k0++) {
        const int kc = k0 * 8;
        uint32_t a[MI][4];
#pragma unroll
        for (int mi = 0; mi < MI; mi++) {
            int r = mbase + mi * 16 + g;
            a[mi][0] = __float_as_uint(As[r * LDA + kc + tig]);
            a[mi][1] = __float_as_uint(As[(r + 8) * LDA + kc + tig]);
            a[mi][2] = __float_as_uint(As[r * LDA + kc + tig + 4]);
            a[mi][3] = __float_as_uint(As[(r + 8) * LDA + kc + tig + 4]);
        }
        uint32_t b[8][2];
#pragma unroll
        for (int ni = 0; ni < 8; ni++) {
            int n = nbase + ni * 8 + g;
            b[ni][0] = __float_as_uint(Bs[n * LDB + kc + tig]);
            b[ni][1] = __float_as_uint(Bs[n * LDB + kc + tig + 4]);
        }
#pragma unroll
        for (int mi = 0; mi < MI; mi++)
#pragma unroll
            for (int ni = 0; ni < 8; ni++)
                mma_tf32(acc[mi][ni], a[mi], b[ni]);
    }

    // ---- epilogue ----
    // float2 stores only when the row stride keeps 8B alignment (DV even).
    constexpr bool VEC2 = (DV % 2 == 0);
#pragma unroll
    for (int mi = 0; mi < MI; mi++) {
#pragma unroll
        for (int ni = 0; ni < 8; ni++) {
            int col = nbase + ni * 8 + 2 * tig;
            float badd0 = 0.f, badd1 = 0.f;
            if (selfhalf) {
                if (col < DV) badd0 = bias[col];
                if (col + 1 < DV) badd1 = bias[col + 1];
            }
            int r_lo = row0 + mbase + mi * 16 + g;
            int r_hi = r_lo + 8;
            if (r_lo < nrows) {
                float v0 = acc[mi][ni][0] + badd0;
                float v1 = acc[mi][ni][1] + badd1;
                if (VEC2 && col + 1 < DV) {
                    *(float2*)&out[(size_t)r_lo * DV + col] = make_float2(v0, v1);
                } else {
                    if (col < DV)     out[(size_t)r_lo * DV + col]     = v0;
                    if (col + 1 < DV) out[(size_t)r_lo * DV + col + 1] = v1;
                }
            }
            if (r_hi < nrows) {
                float v0 = acc[mi][ni][2] + badd0;
                float v1 = acc[mi][ni][3] + badd1;
                if (VEC2 && col + 1 < DV) {
                    *(float2*)&out[(size_t)r_hi * DV + col] = make_float2(v0, v1);
                } else {
                    if (col < DV)     out[(size_t)r_hi * DV + col]     = v0;
                    if (col + 1 < DV) out[(size_t)r_hi * DV + col + 1] = v1;
                }
            }
        }
    }
}

// ---------------- CSR gather aggregation ----------------
__global__ void gather128_kernel(const float* __restrict__ hn,
                                 float* __restrict__ out, int n) {
    int gid = blockIdx.x * blockDim.x + threadIdx.x;
    int node = gid >> 5;
    if (node >= n) return;
    int lane = gid & 31;
    int beg = g_rowstart[node];
    int end = g_rowstart[node + 1];
    float4 acc = make_float4(0.f, 0.f, 0.f, 0.f);
    int j = beg;
    for (; j + 1 < end; j += 2) {
        int s0 = __ldg(&g_esrc[j]);
        int s1 = __ldg(&g_esrc[j + 1]);
        float4 v0 = *(const float4*)&hn[(size_t)s0 * 128 + lane * 4];
        float4 v1 = *(const float4*)&hn[(size_t)s1 * 128 + lane * 4];
        acc.x += v0.x + v1.x; acc.y += v0.y + v1.y;
        acc.z += v0.z + v1.z; acc.w += v0.w + v1.w;
    }
    if (j < end) {
        int s0 = __ldg(&g_esrc[j]);
        float4 v0 = *(const float4*)&hn[(size_t)s0 * 128 + lane * 4];
        acc.x += v0.x; acc.y += v0.y; acc.z += v0.z; acc.w += v0.w;
    }
    float inv = g_invdeg[node];
    float4 o = *(float4*)&out[(size_t)node * 128 + lane * 4];
    o.x += acc.x * inv; o.y += acc.y * inv;
    o.z += acc.z * inv; o.w += acc.w * inv;
    *(float4*)&out[(size_t)node * 128 + lane * 4] = o;
}

__global__ void gather47_kernel(const float* __restrict__ hn,
                                float* __restrict__ out, int n) {
    int gid = blockIdx.x * blockDim.x + threadIdx.x;
    int node = gid >> 5;
    if (node >= n) return;
    int lane = gid & 31;
    int beg = g_rowstart[node];
    int end = g_rowstart[node + 1];
    float acc0 = 0.f, acc1 = 0.f;
    int c1 = lane + 32;
    bool has2 = (c1 < CDIM);
    for (int j = beg; j < end; j++) {
        int s = __ldg(&g_esrc[j]);
        const float* hr = &hn[(size_t)s * CDIM];
        acc0 += hr[lane];
        if (has2) acc1 += hr[c1];
    }
    float inv = g_invdeg[node];
    float* orow = &out[(size_t)node * CDIM];
    orow[lane] += acc0 * inv;
    if (has2) orow[c1] += acc1 * inv;
}

// ---------------- launch ----------------
extern "C" void kernel_launch(void* const* d_in, const int* in_sizes, int n_in,
                              void* d_out, int out_size) {
    const float* x        = (const float*)d_in[0];
    const int*   src      = (const int*)d_in[1];
    const int*   dst      = (const int*)d_in[2];
    const float* w_self0  = (const float*)d_in[3];
    const float* w_neigh0 = (const float*)d_in[4];
    const float* b0       = (const float*)d_in[5];
    const float* w_self1  = (const float*)d_in[6];
    const float* w_neigh1 = (const float*)d_in[7];
    const float* b1       = (const float*)d_in[8];
    const float* w_self2  = (const float*)d_in[9];
    const float* w_neigh2 = (const float*)d_in[10];
    const float* b2       = (const float*)d_in[11];
    float* out = (float*)d_out;

    const int N = in_sizes[0] / DIN;
    const int E = in_sizes[1];

    void *p_h1, *p_h2, *p_hn;
    cudaGetSymbolAddress(&p_h1, g_h1);
    cudaGetSymbolAddress(&p_h2, g_h2);
    cudaGetSymbolAddress(&p_hn, g_hn);
    float* h1 = (float*)p_h1;
    float* h2 = (float*)p_h2;
    float* hn = (float*)p_hn;

    const int SMEM128 = (128 * LDA + 128 * LDB) * sizeof(float);  // 135168
    const int SMEM64  = (128 * LDA + 64 * LDB)  * sizeof(float);  // 101376
    cudaFuncSetAttribute(mma_gemm_kernel<128, 128>,
                         cudaFuncAttributeMaxDynamicSharedMemorySize, SMEM128);
    cudaFuncSetAttribute(mma_gemm_kernel<64, 47>,
                         cudaFuncAttributeMaxDynamicSharedMemorySize, SMEM64);

    dim3 blk(256);
    int nblk = (N + 255) / 256;
    int eblk = (E + 255) / 256;
    int nb_scan = (N + SCAN_B - 1) / SCAN_B;
    long long gthreads = (long long)N * 32;
    int gblk = (int)((gthreads + 255) / 256);
    int mblk = (N + 127) / 128;
    dim3 gg(mblk, 2);

    // degrees + CSR
    zero_deg_kernel<<<nblk, blk>>>(N);
    count_deg_kernel<<<eblk, blk>>>(dst, E);
    inv_deg_kernel<<<nblk, blk>>>(N);
    scan1_kernel<<<nb_scan, SCAN_B>>>(N);
    scan2_kernel<<<1, 512>>>(nb_scan);
    scan3_kernel<<<nblk, blk>>>(N, E);
    fill_kernel<<<eblk, blk>>>(src, dst, E);

    // layer 0: x -> h1 (self+bias), hn (neigh)
    mma_gemm_kernel<128, 128><<<gg, blk, SMEM128>>>(x, w_self0, w_neigh0, b0,
                                                    h1, hn, N, 0);
    gather128_kernel<<<gblk, blk>>>(hn, h1, N);

    // layer 1: relu(h1) -> h2, hn
    mma_gemm_kernel<128, 128><<<gg, blk, SMEM128>>>(h1, w_self1, w_neigh1, b1,
                                                    h2, hn, N, 1);
    gather128_kernel<<<gblk, blk>>>(hn, h2, N);

    // layer 2: relu(h2) -> out (N x 47), hn (N x 47)
    mma_gemm_kernel<64, 47><<<gg, blk, SMEM64>>>(h2, w_self2, w_neigh2, b2,
                                                 out, hn, N, 1);
    gather47_kernel<<<gblk, blk>>>(hn, out, N);
}

// round 11
// speedup vs baseline: 1.9309x; 1.1083x over previous
#include <cuda_runtime.h>
#include <cuda_bf16.h>
#include <cstdint>

#define MAXN 100000
#define MAXE 1700000
#define DIN  128
#define HDIM 128
#define CDIM 47
#define CPAD 48
#define SCAN_B 256
#define NBLK_SCAN ((MAXN + SCAN_B - 1) / SCAN_B)

// ---------------- device scratch (allocation-free) ----------------
__device__ float g_h1[(size_t)MAXN * HDIM];
__device__ float g_h2[(size_t)MAXN * HDIM];
__device__ __nv_bfloat16 g_hn[(size_t)MAXN * HDIM];   // bf16 neighbor transform
__device__ float g_invdeg[MAXN];
__device__ int   g_deg[MAXN];
__device__ int   g_rowstart[MAXN + 1];
__device__ int   g_cursor[MAXN];
__device__ int   g_esrc[MAXE];
__device__ int   g_bsum[NBLK_SCAN];
__device__ int   g_boff[NBLK_SCAN];

// ---------------- degree / CSR build ----------------
__global__ void zero_deg_kernel(int n) {
    int i = blockIdx.x * blockDim.x + threadIdx.x;
    if (i < n) g_deg[i] = 0;
}

__global__ void count_deg_kernel(const int* __restrict__ dst, int e) {
    int i = blockIdx.x * blockDim.x + threadIdx.x;
    if (i < e) atomicAdd(&g_deg[dst[i]], 1);
}

__global__ void inv_deg_kernel(int n) {
    int i = blockIdx.x * blockDim.x + threadIdx.x;
    if (i < n) g_invdeg[i] = 1.0f / fmaxf((float)g_deg[i], 1.0f);
}

__global__ void scan1_kernel(int n) {
    __shared__ int s[SCAN_B];
    int i = blockIdx.x * SCAN_B + threadIdx.x;
    int v = (i < n) ? g_deg[i] : 0;
    s[threadIdx.x] = v;
    __syncthreads();
    for (int off = 1; off < SCAN_B; off <<= 1) {
        int t = (threadIdx.x >= off) ? s[threadIdx.x - off] : 0;
        __syncthreads();
        s[threadIdx.x] += t;
        __syncthreads();
    }
    if (i < n) g_rowstart[i] = s[threadIdx.x] - v;
    if (threadIdx.x == SCAN_B - 1) g_bsum[blockIdx.x] = s[threadIdx.x];
}

__global__ void scan2_kernel(int nb) {
    __shared__ int s[512];
    int v = (threadIdx.x < nb) ? g_bsum[threadIdx.x] : 0;
    s[threadIdx.x] = v;
    __syncthreads();
    for (int off = 1; off < 512; off <<= 1) {
        int t = (threadIdx.x >= off) ? s[threadIdx.x - off] : 0;
        __syncthreads();
        s[threadIdx.x] += t;
        __syncthreads();
    }
    if (threadIdx.x < nb) g_boff[threadIdx.x] = s[threadIdx.x] - v;
}

__global__ void scan3_kernel(int n, int e) {
    int i = blockIdx.x * blockDim.x + threadIdx.x;
    if (i < n) {
        int r = g_rowstart[i] + g_boff[i / SCAN_B];
        g_rowstart[i] = r;
        g_cursor[i] = r;
    }
    if (i == 0) g_rowstart[n] = e;
}

__global__ void fill_kernel(const int* __restrict__ src, const int* __restrict__ dst, int e) {
    int i = blockIdx.x * blockDim.x + threadIdx.x;
    if (i < e) {
        int p = atomicAdd(&g_cursor[dst[i]], 1);
        g_esrc[p] = src[i];
    }
}

// ---------------- tf32 helpers ----------------
__device__ __forceinline__ uint32_t f2tf32(float x) {
    uint32_t r;
    asm("cvt.rna.tf32.f32 %0, %1;" : "=r"(r) : "f"(x));
    return r;
}

__device__ __forceinline__ void mma_tf32(float* c, const uint32_t* a, const uint32_t* b) {
    asm volatile(
        "mma.sync.aligned.m16n8k8.row.col.f32.tf32.tf32.f32 "
        "{%0,%1,%2,%3}, {%4,%5,%6,%7}, {%8,%9}, {%0,%1,%2,%3};"
        : "+f"(c[0]), "+f"(c[1]), "+f"(c[2]), "+f"(c[3])
        : "r"(a[0]), "r"(a[1]), "r"(a[2]), "r"(a[3]), "r"(b[0]), "r"(b[1]));
}

// ---------------- tf32 HMMA GEMM ----------------
// blockIdx.y == 0: out1 (float, stride DV) = A@W1 + bias
// blockIdx.y == 1: out2 (bf16, stride DVP) = A@W2
#define LDA 132
#define LDB 132

template<int BN, int DV, int DVP>
__global__ __launch_bounds__(256, 1)
void mma_gemm_kernel(const float* __restrict__ A,
                     const float* __restrict__ W1, const float* __restrict__ W2,
                     const float* __restrict__ bias,
                     float* __restrict__ out1, __nv_bfloat16* __restrict__ out2,
                     int nrows, int do_relu) {
    extern __shared__ float smem[];
    float* As = smem;               // [128][LDA]
    float* Bs = smem + 128 * LDA;   // [BN][LDB]

    const int tid = threadIdx.x;
    const int row0 = blockIdx.x * 128;
    const bool selfhalf = (blockIdx.y == 0);
    const float* W = selfhalf ? W1 : W2;

    // ---- stage A: relu + tf32 round ----
    for (int f = tid; f < 128 * 32; f += 256) {
        int r = f >> 5;
        int c4 = (f & 31) * 4;
        int row = row0 + r;
        float4 v = make_float4(0.f, 0.f, 0.f, 0.f);
        if (row < nrows) {
            v = *(const float4*)&A[(size_t)row * DIN + c4];
            if (do_relu) {
                v.x = fmaxf(v.x, 0.f); v.y = fmaxf(v.y, 0.f);
                v.z = fmaxf(v.z, 0.f); v.w = fmaxf(v.w, 0.f);
            }
        }
        float* p = &As[r * LDA + c4];
        p[0] = __uint_as_float(f2tf32(v.x));
        p[1] = __uint_as_float(f2tf32(v.y));
        p[2] = __uint_as_float(f2tf32(v.z));
        p[3] = __uint_as_float(f2tf32(v.w));
    }

    // ---- stage B: Bs[n][k] = tf32(W[k][n]) ----
    for (int i = tid; i < 128 * BN; i += 256) {
        int n = i % BN;
        int k = i / BN;
        float v = (n < DV) ? W[(size_t)k * DV + n] : 0.f;
        Bs[n * LDB + k] = __uint_as_float(f2tf32(v));
    }
    __syncthreads();

    // ---- warp tiling ----
    constexpr int WN_CNT = BN / 64;
    constexpr int WM_CNT = 8 / WN_CNT;
    constexpr int TMR = 128 / WM_CNT;
    constexpr int MI = TMR / 16;

    const int wid = tid >> 5;
    const int lane = tid & 31;
    const int g = lane >> 2;
    const int tig = lane & 3;
    const int wm = wid % WM_CNT;
    const int wn = wid / WM_CNT;
    const int mbase = wm * TMR;
    const int nbase = wn * 64;

    float acc[MI][8][4];
#pragma unroll
    for (int mi = 0; mi < MI; mi++)
#pragma unroll
        for (int ni = 0; ni < 8; ni++)
#pragma unroll
            for (int q = 0; q < 4; q++) acc[mi][ni][q] = 0.f;

#pragma unroll
    for (int k0 = 0; k0 < 16; k0++) {
        const int kc = k0 * 8;
        uint32_t a[MI][4];
#pragma unroll
        for (int mi = 0; mi < MI; mi++) {
            int r = mbase + mi * 16 + g;
            a[mi][0] = __float_as_uint(As[r * LDA + kc + tig]);
            a[mi][1] = __float_as_uint(As[(r + 8) * LDA + kc + tig]);
            a[mi][2] = __float_as_uint(As[r * LDA + kc + tig + 4]);
            a[mi][3] = __float_as_uint(As[(r + 8) * LDA + kc + tig + 4]);
        }
        uint32_t b[8][2];
#pragma unroll
        for (int ni = 0; ni < 8; ni++) {
            int n = nbase + ni * 8 + g;
            b[ni][0] = __float_as_uint(Bs[n * LDB + kc + tig]);
            b[ni][1] = __float_as_uint(Bs[n * LDB + kc + tig + 4]);
        }
#pragma unroll
        for (int mi = 0; mi < MI; mi++)
#pragma unroll
            for (int ni = 0; ni < 8; ni++)
                mma_tf32(acc[mi][ni], a[mi], b[ni]);
    }

    // ---- epilogue ----
    constexpr bool VEC2 = (DV % 2 == 0);
#pragma unroll
    for (int mi = 0; mi < MI; mi++) {
#pragma unroll
        for (int ni = 0; ni < 8; ni++) {
            int col = nbase + ni * 8 + 2 * tig;   // even
            int r_lo = row0 + mbase + mi * 16 + g;
            int r_hi = r_lo + 8;
            if (selfhalf) {
                float badd0 = (col < DV) ? bias[col] : 0.f;
                float badd1 = (col + 1 < DV) ? bias[col + 1] : 0.f;
                if (r_lo < nrows) {
                    float v0 = acc[mi][ni][0] + badd0;
                    float v1 = acc[mi][ni][1] + badd1;
                    if (VEC2 && col + 1 < DV) {
                        *(float2*)&out1[(size_t)r_lo * DV + col] = make_float2(v0, v1);
                    } else {
                        if (col < DV)     out1[(size_t)r_lo * DV + col]     = v0;
                        if (col + 1 < DV) out1[(size_t)r_lo * DV + col + 1] = v1;
                    }
                }
                if (r_hi < nrows) {
                    float v0 = acc[mi][ni][2] + badd0;
                    float v1 = acc[mi][ni][3] + badd1;
                    if (VEC2 && col + 1 < DV) {
                        *(float2*)&out1[(size_t)r_hi * DV + col] = make_float2(v0, v1);
                    } else {
                        if (col < DV)     out1[(size_t)r_hi * DV + col]     = v0;
                        if (col + 1 < DV) out1[(size_t)r_hi * DV + col + 1] = v1;
                    }
                }
            } else {
                // bf16x2 store (col even, row stride DVP even -> 4B aligned)
                if (col + 1 < DVP || col + 1 == DVP - 0) {}   // no-op, keep shape
                if (col < DVP) {
                    if (r_lo < nrows) {
                        __nv_bfloat162 v = __float22bfloat162_rn(
                            make_float2(acc[mi][ni][0], acc[mi][ni][1]));
                        *(__nv_bfloat162*)&out2[(size_t)r_lo * DVP + col] = v;
                    }
                    if (r_hi < nrows) {
                        __nv_bfloat162 v = __float22bfloat162_rn(
                            make_float2(acc[mi][ni][2], acc[mi][ni][3]));
                        *(__nv_bfloat162*)&out2[(size_t)r_hi * DVP + col] = v;
                    }
                }
            }
        }
    }
}

// ---------------- CSR gather aggregation (bf16 input, fp32 accum) ----------------
__device__ __forceinline__ void acc_pair(float4& a, uint2 u) {
    __nv_bfloat162 p0 = *(__nv_bfloat162*)&u.x;
    __nv_bfloat162 p1 = *(__nv_bfloat162*)&u.y;
    float2 f0 = __bfloat1622float2(p0);
    float2 f1 = __bfloat1622float2(p1);
    a.x += f0.x; a.y += f0.y; a.z += f1.x; a.w += f1.y;
}

__global__ void gather128_kernel(const __nv_bfloat16* __restrict__ hn,
                                 float* __restrict__ out, int n) {
    int gid = blockIdx.x * blockDim.x + threadIdx.x;
    int node = gid >> 5;
    if (node >= n) return;
    int lane = gid & 31;
    int beg = g_rowstart[node];
    int end = g_rowstart[node + 1];
    float4 acc = make_float4(0.f, 0.f, 0.f, 0.f);
    int j = beg;
    for (; j + 3 < end; j += 4) {
        int s0 = __ldg(&g_esrc[j]);
        int s1 = __ldg(&g_esrc[j + 1]);
        int s2 = __ldg(&g_esrc[j + 2]);
        int s3 = __ldg(&g_esrc[j + 3]);
        uint2 u0 = *(const uint2*)&hn[(size_t)s0 * 128 + lane * 4];
        uint2 u1 = *(const uint2*)&hn[(size_t)s1 * 128 + lane * 4];
        uint2 u2 = *(const uint2*)&hn[(size_t)s2 * 128 + lane * 4];
        uint2 u3 = *(const uint2*)&hn[(size_t)s3 * 128 + lane * 4];
        acc_pair(acc, u0); acc_pair(acc, u1);
        acc_pair(acc, u2); acc_pair(acc, u3);
    }
    for (; j < end; j++) {
        int s0 = __ldg(&g_esrc[j]);
        uint2 u0 = *(const uint2*)&hn[(size_t)s0 * 128 + lane * 4];
        acc_pair(acc, u0);
    }
    float inv = g_invdeg[node];
    float4 o = *(float4*)&out[(size_t)node * 128 + lane * 4];
    o.x += acc.x * inv; o.y += acc.y * inv;
    o.z += acc.z * inv; o.w += acc.w * inv;
    *(float4*)&out[(size_t)node * 128 + lane * 4] = o;
}

// 47-wide: hn rows padded to 48 bf16 (96B). Lanes 0..23 each own one bf16x2.
__global__ void gather47_kernel(const __nv_bfloat16* __restrict__ hn,
                                float* __restrict__ out, int n) {
    int gid = blockIdx.x * blockDim.x + threadIdx.x;
    int node = gid >> 5;
    if (node >= n) return;
    int lane = gid & 31;
    if (lane >= 24) return;
    int beg = g_rowstart[node];
    int end = g_rowstart[node + 1];
    float2 acc = make_float2(0.f, 0.f);
    int j = beg;
    for (; j + 3 < end; j += 4) {
        int s0 = __ldg(&g_esrc[j]);
        int s1 = __ldg(&g_esrc[j + 1]);
        int s2 = __ldg(&g_esrc[j + 2]);
        int s3 = __ldg(&g_esrc[j + 3]);
        uint32_t u0 = *(const uint32_t*)&hn[(size_t)s0 * CPAD + lane * 2];
        uint32_t u1 = *(const uint32_t*)&hn[(size_t)s1 * CPAD + lane * 2];
        uint32_t u2 = *(const uint32_t*)&hn[(size_t)s2 * CPAD + lane * 2];
        uint32_t u3 = *(const uint32_t*)&hn[(size_t)s3 * CPAD + lane * 2];
        float2 f0 = __bfloat1622float2(*(__nv_bfloat162*)&u0);
        float2 f1 = __bfloat1622float2(*(__nv_bfloat162*)&u1);
        float2 f2 = __bfloat1622float2(*(__nv_bfloat162*)&u2);
        float2 f3 = __bfloat1622float2(*(__nv_bfloat162*)&u3);
        acc.x += f0.x + f1.x + f2.x + f3.x;
        acc.y += f0.y + f1.y + f2.y + f3.y;
    }
    for (; j < end; j++) {
        int s0 = __ldg(&g_esrc[j]);
        uint32_t u0 = *(const uint32_t*)&hn[(size_t)s0 * CPAD + lane * 2];
        float2 f0 = __bfloat1622float2(*(__nv_bfloat162*)&u0);
        acc.x += f0.x; acc.y += f0.y;
    }
    float inv = g_invdeg[node];
    int c0 = lane * 2;
    float* orow = &out[(size_t)node * CDIM];
    orow[c0] += acc.x * inv;
    if (c0 + 1 < CDIM) orow[c0 + 1] += acc.y * inv;
}

// ---------------- launch ----------------
extern "C" void kernel_launch(void* const* d_in, const int* in_sizes, int n_in,
                              void* d_out, int out_size) {
    const float* x        = (const float*)d_in[0];
    const int*   src      = (const int*)d_in[1];
    const int*   dst      = (const int*)d_in[2];
    const float* w_self0  = (const float*)d_in[3];
    const float* w_neigh0 = (const float*)d_in[4];
    const float* b0       = (const float*)d_in[5];
    const float* w_self1  = (const float*)d_in[6];
    const float* w_neigh1 = (const float*)d_in[7];
    const float* b1       = (const float*)d_in[8];
    const float* w_self2  = (const float*)d_in[9];
    const float* w_neigh2 = (const float*)d_in[10];
    const float* b2       = (const float*)d_in[11];
    float* out = (float*)d_out;

    const int N = in_sizes[0] / DIN;
    const int E = in_sizes[1];

    void *p_h1, *p_h2, *p_hn;
    cudaGetSymbolAddress(&p_h1, g_h1);
    cudaGetSymbolAddress(&p_h2, g_h2);
    cudaGetSymbolAddress(&p_hn, g_hn);
    float* h1 = (float*)p_h1;
    float* h2 = (float*)p_h2;
    __nv_bfloat16* hn = (__nv_bfloat16*)p_hn;

    const int SMEM128 = (128 * LDA + 128 * LDB) * sizeof(float);  // 135168
    const int SMEM64  = (128 * LDA + 64 * LDB)  * sizeof(float);  // 101376
    cudaFuncSetAttribute(mma_gemm_kernel<128, 128, 128>,
                         cudaFuncAttributeMaxDynamicSharedMemorySize, SMEM128);
    cudaFuncSetAttribute(mma_gemm_kernel<64, 47, 48>,
                         cudaFuncAttributeMaxDynamicSharedMemorySize, SMEM64);

    dim3 blk(256);
    int nblk = (N + 255) / 256;
    int eblk = (E + 255) / 256;
    int nb_scan = (N + SCAN_B - 1) / SCAN_B;
    long long gthreads = (long long)N * 32;
    int gblk = (int)((gthreads + 255) / 256);
    int mblk = (N + 127) / 128;
    dim3 gg(mblk, 2);

    // degrees + CSR
    zero_deg_kernel<<<nblk, blk>>>(N);
    count_deg_kernel<<<eblk, blk>>>(dst, E);
    inv_deg_kernel<<<nblk, blk>>>(N);
    scan1_kernel<<<nb_scan, SCAN_B>>>(N);
    scan2_kernel<<<1, 512>>>(nb_scan);
    scan3_kernel<<<nblk, blk>>>(N, E);
    fill_kernel<<<eblk, blk>>>(src, dst, E);

    // layer 0: x -> h1 (self+bias, fp32), hn (neigh, bf16)
    mma_gemm_kernel<128, 128, 128><<<gg, blk, SMEM128>>>(x, w_self0, w_neigh0, b0,
                                                         h1, hn, N, 0);
    gather128_kernel<<<gblk, blk>>>(hn, h1, N);

    // layer 1: relu(h1) -> h2, hn
    mma_gemm_kernel<128, 128, 128><<<gg, blk, SMEM128>>>(h1, w_self1, w_neigh1, b1,
                                                         h2, hn, N, 1);
    gather128_kernel<<<gblk, blk>>>(hn, h2, N);

    // layer 2: relu(h2) -> out (N x 47 fp32), hn (N x 48 bf16)
    mma_gemm_kernel<64, 47, 48><<<gg, blk, SMEM64>>>(h2, w_self2, w_neigh2, b2,
                                                     out, hn, N, 1);
    gather47_kernel<<<gblk, blk>>>(hn, out, N);
}